// round 1
// baseline (speedup 1.0000x reference)
#include <cuda_runtime.h>
#include <math.h>

// Problem constants
#define NN 8192
#define DD 256
#define XSTR 259   // IN_DIM + P_DIM

// Scratch (device globals: no allocation allowed)
__device__ float4 g_Q4[NN * DD / 4];
__device__ float4 g_K4[NN * DD / 4];
__device__ float4 g_V4[NN * DD / 4];
__device__ float4 g_P4[NN];   // px, py, pz, |p|^2

// Fast exp on the FMA/ALU pipes (avoids MUFU: rt_SMSP=8 would bottleneck).
// Valid for x <= ~80 (our args are always <= 0). Rel err ~3e-6.
__device__ __forceinline__ float fexp(float x) {
    float t = fmaxf(x * 1.4426950408889634f, -126.0f);
    float z = t + 12582912.0f;                  // round-to-nearest-int magic (1.5*2^23)
    float fi = z - 12582912.0f;
    float r  = t - fi;                          // r in [-0.5, 0.5]
    int   e  = __float_as_int(z) - 0x4B400000;  // integer part
    // 2^r = e^(r ln2), Taylor deg-5
    float p = 1.33335581e-3f;
    p = fmaf(p, r, 9.61812911e-3f);
    p = fmaf(p, r, 5.55041087e-2f);
    p = fmaf(p, r, 2.40226507e-1f);
    p = fmaf(p, r, 6.93147182e-1f);
    p = fmaf(p, r, 1.0f);
    return p * __int_as_float((e + 127) << 23);
}

// ---------------------------------------------------------------------------
// Kernel 1: QKV projection.  grid = (128, 3), 256 threads.
// Each block: 64 rows x 256 cols of one of Q/K/V.  8x8 register tile/thread.
// ---------------------------------------------------------------------------
__global__ __launch_bounds__(256) void qkv_kernel(
    const float* __restrict__ X,
    const float* __restrict__ WQ, const float* __restrict__ bQ,
    const float* __restrict__ WK, const float* __restrict__ bK,
    const float* __restrict__ WV, const float* __restrict__ bV)
{
    __shared__ float Xs[64][33];
    __shared__ float Ws[32][256];

    const int mat = blockIdx.y;
    const float* W    = (mat == 0) ? WQ : (mat == 1) ? WK : WV;
    const float* bias = (mat == 0) ? bQ : (mat == 1) ? bK : bV;
    float4* O = (mat == 0) ? g_Q4 : (mat == 1) ? g_K4 : g_V4;

    const int i0 = blockIdx.x * 64;
    const int t = threadIdx.x;
    const int trow = t >> 5, tcol = t & 31;
    const int r0 = trow << 3, c0 = tcol << 3;

    float acc[8][8];
    #pragma unroll
    for (int j = 0; j < 8; j++) {
        float bv = bias[c0 + j];
        #pragma unroll
        for (int i = 0; i < 8; i++) acc[i][j] = bv;
    }

    for (int kk = 0; kk < DD; kk += 32) {
        __syncthreads();
        #pragma unroll
        for (int l = 0; l < 8; l++) {
            int idx = t + l * 256;           // 64*32 elements
            int r = idx >> 5, k = idx & 31;
            Xs[r][k] = X[(i0 + r) * XSTR + kk + k];
        }
        #pragma unroll
        for (int l = 0; l < 32; l++) {
            int idx = t + l * 256;           // 32*256 elements
            int kr = idx >> 8, c = idx & 255;
            Ws[kr][c] = W[(kk + kr) * 256 + c];
        }
        __syncthreads();
        #pragma unroll
        for (int k = 0; k < 32; k++) {
            float xv[8], wv[8];
            #pragma unroll
            for (int i = 0; i < 8; i++) xv[i] = Xs[r0 + i][k];
            float4 w0 = *(const float4*)&Ws[k][c0];
            float4 w1 = *(const float4*)&Ws[k][c0 + 4];
            wv[0]=w0.x; wv[1]=w0.y; wv[2]=w0.z; wv[3]=w0.w;
            wv[4]=w1.x; wv[5]=w1.y; wv[6]=w1.z; wv[7]=w1.w;
            #pragma unroll
            for (int i = 0; i < 8; i++)
                #pragma unroll
                for (int j = 0; j < 8; j++)
                    acc[i][j] = fmaf(xv[i], wv[j], acc[i][j]);
        }
    }

    #pragma unroll
    for (int i = 0; i < 8; i++) {
        int row = i0 + r0 + i;
        O[row * 64 + (c0 >> 2)]     = make_float4(acc[i][0], acc[i][1], acc[i][2], acc[i][3]);
        O[row * 64 + (c0 >> 2) + 1] = make_float4(acc[i][4], acc[i][5], acc[i][6], acc[i][7]);
    }
}

// ---------------------------------------------------------------------------
// Kernel 2: extract positions + squared norms
// ---------------------------------------------------------------------------
__global__ void prep_kernel(const float* __restrict__ X)
{
    int i = blockIdx.x * blockDim.x + threadIdx.x;
    if (i < NN) {
        float px = X[i * XSTR + 256];
        float py = X[i * XSTR + 257];
        float pz = X[i * XSTR + 258];
        g_P4[i] = make_float4(px, py, pz, px * px + py * py + pz * pz);
    }
}

// ---------------------------------------------------------------------------
// Kernel 3: fused flash attention with spatial decay + softmax-one + residual
// grid = 128 blocks (one 64-row stripe each), 256 threads, ~215 KB dyn smem.
// ---------------------------------------------------------------------------
#define BM 64
#define BN 64
#define KST 260   // padded row stride for Qs/Ks/Vs (kills bank conflicts)
#define SST 68    // padded row stride for prob tile

#define SMEM_FLOATS (3 * 64 * KST + 64 * SST + 3 * 64 + 8 * 64)
#define SMEM_BYTES  (SMEM_FLOATS * 4)

__global__ __launch_bounds__(256, 1) void flash_kernel(
    const float* __restrict__ X, float* __restrict__ out)
{
    extern __shared__ float smbuf[];
    float* Qs   = smbuf;               // 64 x KST (pre-scaled by 1/16)
    float* Ks   = Qs + 64 * KST;       // 64 x KST
    float* Vs   = Ks + 64 * KST;       // 64 x KST
    float* Ss   = Vs + 64 * KST;       // 64 x SST  (probabilities)
    float* mrow = Ss + 64 * SST;       // 64 running max
    float* lrow = mrow + 64;           // 64 running sum
    float* srow = lrow + 64;           // 64 rescale factor
    float4* Pq  = (float4*)(srow + 64);   // 64
    float4* Pk  = Pq + 64;                // 64

    const int t  = threadIdx.x;
    const int i0 = blockIdx.x * BM;

    // S-phase mapping: 16x16 thread grid, 4x4 tile, columns interleaved by 16
    const int trow = t >> 4, tcol = t & 15;
    const int r0s = trow << 2;
    // AV-phase mapping: 8x32 thread grid, 8 rows x 8 cols per thread
    const int trow8 = t >> 5, tcol8 = t & 31;
    const int r0a = trow8 << 3, c0a = tcol8 << 3;

    // Load Q stripe (scaled by 1/sqrt(HID)=1/16), init stats
    #pragma unroll
    for (int l = 0; l < 16; l++) {
        int idx = t + l * 256;            // 64*64 float4s
        int r = idx >> 6, kq = idx & 63;
        float4 q = g_Q4[(i0 + r) * 64 + kq];
        q.x *= 0.0625f; q.y *= 0.0625f; q.z *= 0.0625f; q.w *= 0.0625f;
        *(float4*)&Qs[r * KST + (kq << 2)] = q;
    }
    if (t < 64) {
        Pq[t] = g_P4[i0 + t];
        mrow[t] = -1e30f;
        lrow[t] = 0.0f;
    }

    float acc[8][8];
    #pragma unroll
    for (int i = 0; i < 8; i++)
        #pragma unroll
        for (int j = 0; j < 8; j++) acc[i][j] = 0.0f;

    #pragma unroll 1
    for (int j0 = 0; j0 < NN; j0 += BN) {
        __syncthreads();   // previous AV done reading Vs/Ss before overwrite
        #pragma unroll
        for (int l = 0; l < 16; l++) {
            int idx = t + l * 256;
            int r = idx >> 6, kq = idx & 63;
            float4 kv = g_K4[(j0 + r) * 64 + kq];
            *(float4*)&Ks[r * KST + (kq << 2)] = kv;
            float4 vv = g_V4[(j0 + r) * 64 + kq];
            *(float4*)&Vs[r * KST + (kq << 2)] = vv;
        }
        if (t < 64) Pk[t] = g_P4[j0 + t];
        __syncthreads();

        // ---- S = (Q K^T)/16 ----
        float s[4][4];
        #pragma unroll
        for (int i = 0; i < 4; i++)
            #pragma unroll
            for (int j = 0; j < 4; j++) s[i][j] = 0.0f;

        #pragma unroll 4
        for (int k = 0; k < DD; k += 4) {
            float4 a[4], bb[4];
            #pragma unroll
            for (int i = 0; i < 4; i++) a[i]  = *(const float4*)&Qs[(r0s + i) * KST + k];
            #pragma unroll
            for (int j = 0; j < 4; j++) bb[j] = *(const float4*)&Ks[(tcol + 16 * j) * KST + k];
            #pragma unroll
            for (int i = 0; i < 4; i++)
                #pragma unroll
                for (int j = 0; j < 4; j++) {
                    s[i][j] = fmaf(a[i].x, bb[j].x, s[i][j]);
                    s[i][j] = fmaf(a[i].y, bb[j].y, s[i][j]);
                    s[i][j] = fmaf(a[i].z, bb[j].z, s[i][j]);
                    s[i][j] = fmaf(a[i].w, bb[j].w, s[i][j]);
                }
        }

        // ---- spatial decay + online softmax-one stats ----
        #pragma unroll
        for (int i = 0; i < 4; i++) {
            int row = r0s + i;
            float4 pq = Pq[row];
            #pragma unroll
            for (int j = 0; j < 4; j++) {
                float4 pk = Pk[tcol + 16 * j];
                float d2 = pq.w + pk.w - 2.0f * (pq.x*pk.x + pq.y*pk.y + pq.z*pk.z);
                d2 = fmaxf(d2, 0.0f);
                s[i][j] *= fexp(-0.5f * d2);
            }
            float lm = fmaxf(fmaxf(s[i][0], s[i][1]), fmaxf(s[i][2], s[i][3]));
            #pragma unroll
            for (int off = 1; off < 16; off <<= 1)
                lm = fmaxf(lm, __shfl_xor_sync(0xffffffffu, lm, off));
            float mo = mrow[row];
            float mn = fmaxf(mo, lm);
            float rs = 0.0f;
            #pragma unroll
            for (int j = 0; j < 4; j++) {
                float p = fexp(s[i][j] - mn);
                Ss[row * SST + tcol + 16 * j] = p;
                rs += p;
            }
            #pragma unroll
            for (int off = 1; off < 16; off <<= 1)
                rs += __shfl_xor_sync(0xffffffffu, rs, off);
            if (tcol == 0) {
                float sc = fexp(mo - mn);
                lrow[row] = lrow[row] * sc + rs;
                mrow[row] = mn;
                srow[row] = sc;
            }
        }
        __syncthreads();

        // ---- AV accumulation (with online rescale) ----
        #pragma unroll
        for (int i = 0; i < 8; i++) {
            float sc = srow[r0a + i];
            #pragma unroll
            for (int j = 0; j < 8; j++) acc[i][j] *= sc;
        }
        #pragma unroll 2
        for (int jj = 0; jj < BN; jj++) {
            float p[8];
            #pragma unroll
            for (int i = 0; i < 8; i++) p[i] = Ss[(r0a + i) * SST + jj];
            float4 v0 = *(const float4*)&Vs[jj * KST + c0a];
            float4 v1 = *(const float4*)&Vs[jj * KST + c0a + 4];
            #pragma unroll
            for (int i = 0; i < 8; i++) {
                acc[i][0] = fmaf(p[i], v0.x, acc[i][0]);
                acc[i][1] = fmaf(p[i], v0.y, acc[i][1]);
                acc[i][2] = fmaf(p[i], v0.z, acc[i][2]);
                acc[i][3] = fmaf(p[i], v0.w, acc[i][3]);
                acc[i][4] = fmaf(p[i], v1.x, acc[i][4]);
                acc[i][5] = fmaf(p[i], v1.y, acc[i][5]);
                acc[i][6] = fmaf(p[i], v1.z, acc[i][6]);
                acc[i][7] = fmaf(p[i], v1.w, acc[i][7]);
            }
        }
    }

    // ---- epilogue: H = acc/(1+l) + Xf ----
    #pragma unroll
    for (int i = 0; i < 8; i++) {
        int row = i0 + r0a + i;
        float inv = 1.0f / (1.0f + lrow[r0a + i]);
        float o[8];
        #pragma unroll
        for (int j = 0; j < 8; j++)
            o[j] = acc[i][j] * inv + X[row * XSTR + c0a + j];
        *(float4*)&out[row * DD + c0a]     = make_float4(o[0], o[1], o[2], o[3]);
        *(float4*)&out[row * DD + c0a + 4] = make_float4(o[4], o[5], o[6], o[7]);
    }
}

// ---------------------------------------------------------------------------
extern "C" void kernel_launch(void* const* d_in, const int* in_sizes, int n_in,
                              void* d_out, int out_size)
{
    const float* X  = (const float*)d_in[0];
    const float* WQ = (const float*)d_in[1];
    const float* bQ = (const float*)d_in[2];
    const float* WK = (const float*)d_in[3];
    const float* bK = (const float*)d_in[4];
    const float* WV = (const float*)d_in[5];
    const float* bV = (const float*)d_in[6];
    float* out = (float*)d_out;

    cudaFuncSetAttribute(flash_kernel,
                         cudaFuncAttributeMaxDynamicSharedMemorySize, SMEM_BYTES);

    qkv_kernel<<<dim3(NN / 64, 3), 256>>>(X, WQ, bQ, WK, bK, WV, bV);
    prep_kernel<<<NN / 256, 256>>>(X);
    flash_kernel<<<NN / BM, 256, SMEM_BYTES>>>(X, out);
}

// round 3
// speedup vs baseline: 5.2573x; 5.2573x over previous
#include <cuda_runtime.h>
#include <cuda_bf16.h>
#include <cstdint>

#define NN 8192
#define DD 256
#define XSTR 259

// ---------------- device scratch ----------------
__device__ __nv_bfloat16 g_Qbf[NN * DD];   // Q * 1/16, bf16 row-major
__device__ __nv_bfloat16 g_Kbf[NN * DD];   // K bf16 row-major
__device__ __nv_bfloat16 g_Vbf[NN * DD];   // V bf16 row-major
__device__ float4 g_P4[NN];                // px,py,pz,|p|^2

// ---------------- helpers ----------------
__device__ __forceinline__ uint32_t smem_u32(const void* p) {
    uint32_t a;
    asm("{ .reg .u64 t; cvta.to.shared.u64 t, %1; cvt.u32.u64 %0, t; }" : "=r"(a) : "l"(p));
    return a;
}
__device__ __forceinline__ uint32_t pack_bf16(float lo, float hi) {
    uint32_t r;
    asm("cvt.rn.bf16x2.f32 %0, %1, %2;" : "=r"(r) : "f"(hi), "f"(lo));
    return r;
}
__device__ __forceinline__ void cp16(uint32_t s, const void* g) {
    asm volatile("cp.async.cg.shared.global [%0], [%1], 16;" :: "r"(s), "l"(g));
}
__device__ __forceinline__ void ldm4(uint32_t* r, uint32_t a) {
    asm volatile("ldmatrix.sync.aligned.m8n8.x4.shared.b16 {%0,%1,%2,%3}, [%4];"
                 : "=r"(r[0]), "=r"(r[1]), "=r"(r[2]), "=r"(r[3]) : "r"(a));
}
__device__ __forceinline__ void ldm4t(uint32_t* r, uint32_t a) {
    asm volatile("ldmatrix.sync.aligned.m8n8.x4.trans.shared.b16 {%0,%1,%2,%3}, [%4];"
                 : "=r"(r[0]), "=r"(r[1]), "=r"(r[2]), "=r"(r[3]) : "r"(a));
}
__device__ __forceinline__ void mma16816(float* c, const uint32_t* a, uint32_t b0, uint32_t b1) {
    asm volatile(
        "mma.sync.aligned.m16n8k16.row.col.f32.bf16.bf16.f32 "
        "{%0,%1,%2,%3}, {%4,%5,%6,%7}, {%8,%9}, {%0,%1,%2,%3};"
        : "+f"(c[0]), "+f"(c[1]), "+f"(c[2]), "+f"(c[3])
        : "r"(a[0]), "r"(a[1]), "r"(a[2]), "r"(a[3]), "r"(b0), "r"(b1));
}

// ---------------------------------------------------------------------------
// K1: QKV projection (fp32 SIMT) -> bf16 Q/16, K, V (row-major)
// ---------------------------------------------------------------------------
__global__ __launch_bounds__(256) void qkv_kernel(
    const float* __restrict__ X,
    const float* __restrict__ WQ, const float* __restrict__ bQ,
    const float* __restrict__ WK, const float* __restrict__ bK,
    const float* __restrict__ WV, const float* __restrict__ bV)
{
    __shared__ float Xs[64][33];
    __shared__ float Ws[32][256];

    const int mat = blockIdx.y;
    const float* W    = (mat == 0) ? WQ : (mat == 1) ? WK : WV;
    const float* bias = (mat == 0) ? bQ : (mat == 1) ? bK : bV;
    __nv_bfloat16* O  = (mat == 0) ? g_Qbf : (mat == 1) ? g_Kbf : g_Vbf;
    const float sc    = (mat == 0) ? 0.0625f : 1.0f;

    const int i0 = blockIdx.x * 64;
    const int t = threadIdx.x;
    const int trow = t >> 5, tcol = t & 31;
    const int r0 = trow << 3, c0 = tcol << 3;

    float acc[8][8];
    #pragma unroll
    for (int j = 0; j < 8; j++) {
        float bv = bias[c0 + j];
        #pragma unroll
        for (int i = 0; i < 8; i++) acc[i][j] = bv;
    }

    for (int kk = 0; kk < DD; kk += 32) {
        __syncthreads();
        #pragma unroll
        for (int l = 0; l < 8; l++) {
            int idx = t + l * 256;
            int r = idx >> 5, k = idx & 31;
            Xs[r][k] = X[(i0 + r) * XSTR + kk + k];
        }
        #pragma unroll
        for (int l = 0; l < 32; l++) {
            int idx = t + l * 256;
            int kr = idx >> 8, c = idx & 255;
            Ws[kr][c] = W[(kk + kr) * 256 + c];
        }
        __syncthreads();
        #pragma unroll
        for (int k = 0; k < 32; k++) {
            float xv[8], wv[8];
            #pragma unroll
            for (int i = 0; i < 8; i++) xv[i] = Xs[r0 + i][k];
            float4 w0 = *(const float4*)&Ws[k][c0];
            float4 w1 = *(const float4*)&Ws[k][c0 + 4];
            wv[0]=w0.x; wv[1]=w0.y; wv[2]=w0.z; wv[3]=w0.w;
            wv[4]=w1.x; wv[5]=w1.y; wv[6]=w1.z; wv[7]=w1.w;
            #pragma unroll
            for (int i = 0; i < 8; i++)
                #pragma unroll
                for (int j = 0; j < 8; j++)
                    acc[i][j] = fmaf(xv[i], wv[j], acc[i][j]);
        }
    }

    #pragma unroll
    for (int i = 0; i < 8; i++) {
        uint4 u;
        u.x = pack_bf16(acc[i][0]*sc, acc[i][1]*sc);
        u.y = pack_bf16(acc[i][2]*sc, acc[i][3]*sc);
        u.z = pack_bf16(acc[i][4]*sc, acc[i][5]*sc);
        u.w = pack_bf16(acc[i][6]*sc, acc[i][7]*sc);
        *(uint4*)&O[(size_t)(i0 + r0 + i) * DD + c0] = u;
    }
}

// ---------------------------------------------------------------------------
// K2: positions
// ---------------------------------------------------------------------------
__global__ void prep_kernel(const float* __restrict__ X)
{
    int i = blockIdx.x * blockDim.x + threadIdx.x;
    if (i < NN) {
        float px = X[i * XSTR + 256];
        float py = X[i * XSTR + 257];
        float pz = X[i * XSTR + 258];
        g_P4[i] = make_float4(px, py, pz, px*px + py*py + pz*pz);
    }
}

// ---------------------------------------------------------------------------
// K3: single-pass flash attention, mma.sync bf16
// grid 128 CTAs x 64 rows; 256 threads (8 warps: 4 row-groups x 2 col-halves)
// ---------------------------------------------------------------------------
// smem layout (bytes). K/V/Q row stride = 264 halves = 528 B (33 x 16B, odd -> conflict-free)
#define SQ   0                       // 64*528 = 33792
#define SK   33792                   // 2 bufs x 33792
#define SV   101376                  // 2 bufs x 33792
#define SP   168960                  // P tile 64 x 72 halves (144B) = 9216
#define SPK  178176                  // pk 2 bufs x 64 x 16B = 2048
#define SRM  180224                  // redM [2][64] f32 = 512
#define SRS  180736                  // redS [2][64] f32 = 512
#define SMEMB 181248

__device__ __forceinline__ void load_tile(uint32_t sb, int t, int tt)
{
    const int b = tt & 1;
    const int j0 = tt * 64;
    #pragma unroll
    for (int l = 0; l < 8; l++) {
        int idx = t + l * 256;
        int r = idx >> 5, c8 = idx & 31;
        size_t goff = ((size_t)(j0 + r) * DD + c8 * 8) * 2;
        uint32_t soff = (uint32_t)(r * 528 + c8 * 16);
        cp16(sb + SK + b * 33792 + soff, (const char*)g_Kbf + goff);
        cp16(sb + SV + b * 33792 + soff, (const char*)g_Vbf + goff);
    }
    if (t < 64) cp16(sb + SPK + b * 1024 + t * 16, &g_P4[j0 + t]);
    asm volatile("cp.async.commit_group;" ::: "memory");
}

__global__ __launch_bounds__(256, 1) void flash_kernel(
    const float* __restrict__ X, float* __restrict__ out)
{
    extern __shared__ char sm[];
    const uint32_t sb = smem_u32(sm);
    const int t = threadIdx.x;
    const int lane = t & 31, w = t >> 5;
    const int rg = w & 3, ch = w >> 2;
    const int g = lane >> 2, t4 = lane & 3;
    const int i0 = blockIdx.x * 64;
    const int rA = rg * 16 + g, rB = rA + 8;   // local rows

    float* redM = (float*)(sm + SRM);
    float* redS = (float*)(sm + SRS);

    // stage Q (64 x 256 bf16)
    #pragma unroll
    for (int l = 0; l < 8; l++) {
        int idx = t + l * 256;
        int r = idx >> 5, c8 = idx & 31;
        uint4 v = *(const uint4*)((const char*)g_Qbf + ((size_t)(i0 + r) * DD + c8 * 8) * 2);
        *(uint4*)(sm + SQ + r * 528 + c8 * 16) = v;
    }
    load_tile(sb, t, 0);
    load_tile(sb, t, 1);

    const float4 pqA = g_P4[i0 + rA];
    const float4 pqB = g_P4[i0 + rB];

    __syncthreads();

    // hoist Q a-frags: 16 k-steps x 4 regs
    uint32_t Qa[16][4];
    {
        uint32_t base = sb + SQ + (rg * 16 + (lane & 15)) * 528 + ((lane >> 4) * 8) * 2;
        #pragma unroll
        for (int k = 0; k < 16; k++) ldm4(Qa[k], base + k * 32);
    }

    float o[16][4];
    #pragma unroll
    for (int i = 0; i < 16; i++)
        #pragma unroll
        for (int j = 0; j < 4; j++) o[i][j] = 0.f;
    float mA = -1e30f, mB = -1e30f, lA = 0.f, lB = 0.f;

    #pragma unroll 1
    for (int tt = 0; tt < 128; tt++) {
        const int b = tt & 1;
        asm volatile("cp.async.wait_group 1;" ::: "memory");
        __syncthreads();

        // ---- S = Q K^T (per warp: 16 x 32) ----
        const uint32_t kbase = sb + SK + b * 33792;
        float s[4][4];
        #pragma unroll
        for (int i = 0; i < 4; i++)
            #pragma unroll
            for (int j = 0; j < 4; j++) s[i][j] = 0.f;

        const int krow_off = ((lane >> 4) << 3) + (lane & 7);
        const int kcol_off = ((lane >> 3) & 1) * 8;
        #pragma unroll
        for (int k = 0; k < 16; k++) {
            #pragma unroll
            for (int np = 0; np < 2; np++) {
                int row = ch * 32 + np * 16 + krow_off;
                int col = k * 16 + kcol_off;
                uint32_t bf[4];
                ldm4(bf, kbase + row * 528 + col * 2);
                mma16816(s[np * 2],     Qa[k], bf[0], bf[1]);
                mma16816(s[np * 2 + 1], Qa[k], bf[2], bf[3]);
            }
        }

        // ---- decay + local max ----
        const float4* pk = (const float4*)(sm + SPK + b * 1024);
        float mxA = -1e30f, mxB = -1e30f;
        #pragma unroll
        for (int nb = 0; nb < 4; nb++) {
            int c0 = ch * 32 + nb * 8 + t4 * 2;
            float4 k0 = pk[c0], k1 = pk[c0 + 1];
            float dA0 = fmaxf(pqA.w + k0.w - 2.f*(pqA.x*k0.x + pqA.y*k0.y + pqA.z*k0.z), 0.f);
            float dA1 = fmaxf(pqA.w + k1.w - 2.f*(pqA.x*k1.x + pqA.y*k1.y + pqA.z*k1.z), 0.f);
            float dB0 = fmaxf(pqB.w + k0.w - 2.f*(pqB.x*k0.x + pqB.y*k0.y + pqB.z*k0.z), 0.f);
            float dB1 = fmaxf(pqB.w + k1.w - 2.f*(pqB.x*k1.x + pqB.y*k1.y + pqB.z*k1.z), 0.f);
            s[nb][0] *= __expf(-0.5f * dA0);
            s[nb][1] *= __expf(-0.5f * dA1);
            s[nb][2] *= __expf(-0.5f * dB0);
            s[nb][3] *= __expf(-0.5f * dB1);
            mxA = fmaxf(mxA, fmaxf(s[nb][0], s[nb][1]));
            mxB = fmaxf(mxB, fmaxf(s[nb][2], s[nb][3]));
        }
        #pragma unroll
        for (int off = 1; off < 4; off <<= 1) {
            mxA = fmaxf(mxA, __shfl_xor_sync(0xffffffffu, mxA, off));
            mxB = fmaxf(mxB, __shfl_xor_sync(0xffffffffu, mxB, off));
        }
        if (t4 == 0) { redM[ch * 64 + rA] = mxA; redM[ch * 64 + rB] = mxB; }
        __syncthreads();
        float nMA = fmaxf(fmaxf(mA, mxA), redM[(1 - ch) * 64 + rA]);
        float nMB = fmaxf(fmaxf(mB, mxB), redM[(1 - ch) * 64 + rB]);
        float sclA = __expf(mA - nMA);
        float sclB = __expf(mB - nMB);

        // ---- P = exp(s - m), store bf16, partial sums ----
        float smA = 0.f, smB = 0.f;
        #pragma unroll
        for (int nb = 0; nb < 4; nb++) {
            int c0 = ch * 32 + nb * 8 + t4 * 2;
            float p0 = __expf(s[nb][0] - nMA);
            float p1 = __expf(s[nb][1] - nMA);
            float p2 = __expf(s[nb][2] - nMB);
            float p3 = __expf(s[nb][3] - nMB);
            smA += p0 + p1; smB += p2 + p3;
            *(uint32_t*)(sm + SP + rA * 144 + c0 * 2) = pack_bf16(p0, p1);
            *(uint32_t*)(sm + SP + rB * 144 + c0 * 2) = pack_bf16(p2, p3);
        }
        #pragma unroll
        for (int off = 1; off < 4; off <<= 1) {
            smA += __shfl_xor_sync(0xffffffffu, smA, off);
            smB += __shfl_xor_sync(0xffffffffu, smB, off);
        }
        if (t4 == 0) { redS[ch * 64 + rA] = smA; redS[ch * 64 + rB] = smB; }
        __syncthreads();
        lA = lA * sclA + smA + redS[(1 - ch) * 64 + rA];
        lB = lB * sclB + smB + redS[(1 - ch) * 64 + rB];
        mA = nMA; mB = nMB;
        #pragma unroll
        for (int nb = 0; nb < 16; nb++) {
            o[nb][0] *= sclA; o[nb][1] *= sclA;
            o[nb][2] *= sclB; o[nb][3] *= sclB;
        }

        // ---- O += P V (per warp: 16 x 128) ----
        const uint32_t vbase = sb + SV + b * 33792;
        const int vrow_off = ((lane >> 3) & 1) * 8 + (lane & 7);
        const int vcol_off = (lane >> 4) * 8;
        #pragma unroll
        for (int k = 0; k < 4; k++) {
            uint32_t Pa[4];
            ldm4(Pa, sb + SP + (rg * 16 + (lane & 15)) * 144 + (k * 16 + (lane >> 4) * 8) * 2);
            #pragma unroll
            for (int n16 = 0; n16 < 8; n16++) {
                int vr = k * 16 + vrow_off;
                int vc = ch * 128 + n16 * 16 + vcol_off;
                uint32_t vb[4];
                ldm4t(vb, vbase + vr * 528 + vc * 2);
                mma16816(o[n16 * 2],     Pa, vb[0], vb[1]);
                mma16816(o[n16 * 2 + 1], Pa, vb[2], vb[3]);
            }
        }
        __syncthreads();
        if (tt + 2 < 128) load_tile(sb, t, tt + 2);
        else asm volatile("cp.async.commit_group;" ::: "memory");
    }

    // ---- epilogue: normalize + residual ----
    const float iA = 1.f / (1.f + lA);
    const float iB = 1.f / (1.f + lB);
    const int gA = i0 + rA, gB = i0 + rB;
    #pragma unroll
    for (int nb = 0; nb < 16; nb++) {
        int c = ch * 128 + nb * 8 + t4 * 2;
        float2 vA = make_float2(o[nb][0] * iA + X[(size_t)gA * XSTR + c],
                                o[nb][1] * iA + X[(size_t)gA * XSTR + c + 1]);
        *(float2*)&out[(size_t)gA * DD + c] = vA;
        float2 vB = make_float2(o[nb][2] * iB + X[(size_t)gB * XSTR + c],
                                o[nb][3] * iB + X[(size_t)gB * XSTR + c + 1]);
        *(float2*)&out[(size_t)gB * DD + c] = vB;
    }
}

// ---------------------------------------------------------------------------
extern "C" void kernel_launch(void* const* d_in, const int* in_sizes, int n_in,
                              void* d_out, int out_size)
{
    const float* X  = (const float*)d_in[0];
    const float* WQ = (const float*)d_in[1];
    const float* bQ = (const float*)d_in[2];
    const float* WK = (const float*)d_in[3];
    const float* bK = (const float*)d_in[4];
    const float* WV = (const float*)d_in[5];
    const float* bV = (const float*)d_in[6];
    float* out = (float*)d_out;

    cudaFuncSetAttribute(flash_kernel,
                         cudaFuncAttributeMaxDynamicSharedMemorySize, SMEMB);

    qkv_kernel<<<dim3(NN / 64, 3), 256>>>(X, WQ, bQ, WK, bK, WV, bV);
    prep_kernel<<<NN / 256, 256>>>(X);
    flash_kernel<<<NN / 64, 256, SMEMB>>>(X, out);
}

// round 5
// speedup vs baseline: 5.9823x; 1.1379x over previous
#include <cuda_runtime.h>
#include <cuda_bf16.h>
#include <cstdint>

#define NN 8192
#define DD 256
#define XSTR 259

// ---------------- device scratch ----------------
__device__ __nv_bfloat16 g_Xbf[NN * DD];      // X features bf16
__device__ __nv_bfloat16 g_Wbf[3][DD * DD];   // W bf16 [k][n] (Q folded w/ 1/16)
__device__ __nv_bfloat16 g_Qbf[NN * DD];      // Q/16 bf16
__device__ __nv_bfloat16 g_Kbf[NN * DD];
__device__ __nv_bfloat16 g_Vbf[NN * DD];
__device__ float4 g_P4[NN];                   // px,py,pz,|p|^2

// ---------------- helpers ----------------
__device__ __forceinline__ uint32_t smem_u32(const void* p) {
    uint32_t a;
    asm("{ .reg .u64 t; cvta.to.shared.u64 t, %1; cvt.u32.u64 %0, t; }" : "=r"(a) : "l"(p));
    return a;
}
__device__ __forceinline__ uint32_t pack_bf16(float lo, float hi) {
    uint32_t r;
    asm("cvt.rn.bf16x2.f32 %0, %1, %2;" : "=r"(r) : "f"(hi), "f"(lo));
    return r;
}
__device__ __forceinline__ void cp16(uint32_t s, const void* g) {
    asm volatile("cp.async.cg.shared.global [%0], [%1], 16;" :: "r"(s), "l"(g));
}
__device__ __forceinline__ void ldm4(uint32_t* r, uint32_t a) {
    asm volatile("ldmatrix.sync.aligned.m8n8.x4.shared.b16 {%0,%1,%2,%3}, [%4];"
                 : "=r"(r[0]), "=r"(r[1]), "=r"(r[2]), "=r"(r[3]) : "r"(a));
}
__device__ __forceinline__ void ldm4t(uint32_t* r, uint32_t a) {
    asm volatile("ldmatrix.sync.aligned.m8n8.x4.trans.shared.b16 {%0,%1,%2,%3}, [%4];"
                 : "=r"(r[0]), "=r"(r[1]), "=r"(r[2]), "=r"(r[3]) : "r"(a));
}
__device__ __forceinline__ void mma16816(float* c, const uint32_t* a, uint32_t b0, uint32_t b1) {
    asm volatile(
        "mma.sync.aligned.m16n8k16.row.col.f32.bf16.bf16.f32 "
        "{%0,%1,%2,%3}, {%4,%5,%6,%7}, {%8,%9}, {%0,%1,%2,%3};"
        : "+f"(c[0]), "+f"(c[1]), "+f"(c[2]), "+f"(c[3])
        : "r"(a[0]), "r"(a[1]), "r"(a[2]), "r"(a[3]), "r"(b0), "r"(b1));
}

// ---------------------------------------------------------------------------
// K0: prep — X -> bf16, positions.  (X rows are only 4B-aligned: scalar loads!)
// ---------------------------------------------------------------------------
__global__ __launch_bounds__(256) void prep_kernel(const float* __restrict__ X)
{
    int idx = blockIdx.x * 256 + threadIdx.x;       // 8192*32
    int row = idx >> 5, c8 = idx & 31;
    const float* xr = X + (size_t)row * XSTR + c8 * 8;
    float v0 = xr[0], v1 = xr[1], v2 = xr[2], v3 = xr[3];
    float v4 = xr[4], v5 = xr[5], v6 = xr[6], v7 = xr[7];
    uint4 u;
    u.x = pack_bf16(v0, v1); u.y = pack_bf16(v2, v3);
    u.z = pack_bf16(v4, v5); u.w = pack_bf16(v6, v7);
    *(uint4*)&g_Xbf[(size_t)row * DD + c8 * 8] = u;
    if (c8 == 0) {
        float px = X[(size_t)row * XSTR + 256];
        float py = X[(size_t)row * XSTR + 257];
        float pz = X[(size_t)row * XSTR + 258];
        g_P4[row] = make_float4(px, py, pz, px*px + py*py + pz*pz);
    }
}

// ---------------------------------------------------------------------------
// K0b: W -> bf16 (Q folded with 1/16)
// ---------------------------------------------------------------------------
__global__ __launch_bounds__(256) void wconv_kernel(
    const float* __restrict__ WQ, const float* __restrict__ WK, const float* __restrict__ WV)
{
    int mat = blockIdx.y;
    const float* W = (mat == 0) ? WQ : (mat == 1) ? WK : WV;
    float sc = (mat == 0) ? 0.0625f : 1.0f;
    int idx = blockIdx.x * 256 + threadIdx.x;
    int base = idx * 8;
    const float4* wr = (const float4*)(W + base);
    float4 a = wr[0], b = wr[1];
    uint4 u;
    u.x = pack_bf16(a.x*sc, a.y*sc); u.y = pack_bf16(a.z*sc, a.w*sc);
    u.z = pack_bf16(b.x*sc, b.y*sc); u.w = pack_bf16(b.z*sc, b.w*sc);
    *(uint4*)&g_Wbf[mat][base] = u;
}

// ---------------------------------------------------------------------------
// K1: QKV via mma.sync.  grid (64, 3), 256 thr, warp = 16 rows x 256 cols
// ---------------------------------------------------------------------------
#define QX 0                  // 128 x 528
#define QW 67584              // 256 x 528
#define SMEMQ (67584 + 135168)

__global__ __launch_bounds__(256, 1) void qkv_mma_kernel(
    const float* __restrict__ bQ, const float* __restrict__ bK, const float* __restrict__ bV)
{
    extern __shared__ char sm[];
    const uint32_t sb = smem_u32(sm);
    const int t = threadIdx.x, lane = t & 31, w = t >> 5;
    const int g = lane >> 2, t4 = lane & 3;
    const int mat = blockIdx.y;
    const int i0 = blockIdx.x * 128;
    const float* bias = (mat == 0) ? bQ : (mat == 1) ? bK : bV;
    const float bsc = (mat == 0) ? 0.0625f : 1.0f;
    __nv_bfloat16* O = (mat == 0) ? g_Qbf : (mat == 1) ? g_Kbf : g_Vbf;

    #pragma unroll
    for (int l = 0; l < 16; l++) {
        int idx = t + l * 256;
        int r = idx >> 5, c8 = idx & 31;
        uint4 v = *(const uint4*)&g_Xbf[(size_t)(i0 + r) * DD + c8 * 8];
        *(uint4*)(sm + QX + r * 528 + c8 * 16) = v;
    }
    #pragma unroll
    for (int l = 0; l < 32; l++) {
        int idx = t + l * 256;
        int r = idx >> 5, c8 = idx & 31;
        uint4 v = *(const uint4*)&g_Wbf[mat][(size_t)r * DD + c8 * 8];
        *(uint4*)(sm + QW + r * 528 + c8 * 16) = v;
    }
    __syncthreads();

    float o[32][4];
    #pragma unroll
    for (int i = 0; i < 32; i++)
        #pragma unroll
        for (int j = 0; j < 4; j++) o[i][j] = 0.f;

    const int arow = w * 16 + (lane & 15);
    const int acol = (lane >> 4) * 8;
    const int vrow_off = ((lane >> 3) & 1) * 8 + (lane & 7);
    const int vcol_off = (lane >> 4) * 8;

    #pragma unroll
    for (int k = 0; k < 16; k++) {
        uint32_t Aa[4];
        ldm4(Aa, sb + QX + arow * 528 + (acol + k * 16) * 2);
        #pragma unroll
        for (int n16 = 0; n16 < 16; n16++) {
            uint32_t vb[4];
            ldm4t(vb, sb + QW + (k * 16 + vrow_off) * 528 + (n16 * 16 + vcol_off) * 2);
            mma16816(o[n16 * 2],     Aa, vb[0], vb[1]);
            mma16816(o[n16 * 2 + 1], Aa, vb[2], vb[3]);
        }
    }

    const int row0 = i0 + w * 16 + g;
    #pragma unroll
    for (int nb = 0; nb < 32; nb++) {
        int c = nb * 8 + t4 * 2;
        float b0 = bias[c] * bsc, b1 = bias[c + 1] * bsc;
        *(uint32_t*)&O[(size_t)row0 * DD + c]       = pack_bf16(o[nb][0] + b0, o[nb][1] + b1);
        *(uint32_t*)&O[(size_t)(row0 + 8) * DD + c] = pack_bf16(o[nb][2] + b0, o[nb][3] + b1);
    }
}

// ---------------------------------------------------------------------------
// K2: flash attention, register-resident P, per-half online softmax
// grid 128 CTAs x 64 rows; 8 warps = (rg 0..3) x (key-half ch 0..1)
// ---------------------------------------------------------------------------
#define SQ   0                       // 64*528 = 33792
#define SK   33792                   // 2 x 33792
#define SV   101376                  // 2 x 33792
#define SPK  168960                  // 2 x 1024
#define SMEMB 171008
// merge area (after loop): oM f32 [64][260] at 0; m/l at 68608

__device__ __forceinline__ void load_tile(uint32_t sb, int t, int tt)
{
    const int b = tt & 1;
    const int j0 = tt * 64;
    #pragma unroll
    for (int l = 0; l < 8; l++) {
        int idx = t + l * 256;
        int r = idx >> 5, c8 = idx & 31;
        size_t goff = ((size_t)(j0 + r) * DD + c8 * 8) * 2;
        uint32_t soff = (uint32_t)(r * 528 + c8 * 16);
        cp16(sb + SK + b * 33792 + soff, (const char*)g_Kbf + goff);
        cp16(sb + SV + b * 33792 + soff, (const char*)g_Vbf + goff);
    }
    if (t < 64) cp16(sb + SPK + b * 1024 + t * 16, &g_P4[j0 + t]);
    asm volatile("cp.async.commit_group;" ::: "memory");
}

__global__ __launch_bounds__(256, 1) void flash_kernel(
    const float* __restrict__ X, float* __restrict__ out)
{
    extern __shared__ char sm[];
    const uint32_t sb = smem_u32(sm);
    const int t = threadIdx.x;
    const int lane = t & 31, w = t >> 5;
    const int rg = w & 3, ch = w >> 2;
    const int g = lane >> 2, t4 = lane & 3;
    const int i0 = blockIdx.x * 64;
    const int rA = rg * 16 + g, rB = rA + 8;

    // stage Q
    #pragma unroll
    for (int l = 0; l < 8; l++) {
        int idx = t + l * 256;
        int r = idx >> 5, c8 = idx & 31;
        uint4 v = *(const uint4*)&g_Qbf[(size_t)(i0 + r) * DD + c8 * 8];
        *(uint4*)(sm + SQ + r * 528 + c8 * 16) = v;
    }
    load_tile(sb, t, 0);
    load_tile(sb, t, 1);

    const float4 pqA = g_P4[i0 + rA];
    const float4 pqB = g_P4[i0 + rB];

    float o[32][4];
    #pragma unroll
    for (int i = 0; i < 32; i++)
        #pragma unroll
        for (int j = 0; j < 4; j++) o[i][j] = 0.f;
    float mA = -1e30f, mB = -1e30f, lA = 0.f, lB = 0.f;

    const int qrow = rg * 16 + (lane & 15);
    const int qcol = (lane >> 4) * 8;
    const int krow_off = ((lane >> 4) << 3) + (lane & 7);
    const int kcol_off = ((lane >> 3) & 1) * 8;
    const int vrow_off = ((lane >> 3) & 1) * 8 + (lane & 7);
    const int vcol_off = (lane >> 4) * 8;

    __syncthreads();

    #pragma unroll 1
    for (int tt = 0; tt < 128; tt++) {
        const int b = tt & 1;
        asm volatile("cp.async.wait_group 1;" ::: "memory");
        __syncthreads();

        // ---- S = Q K^T (warp: 16 rows x 32 keys of its half) ----
        const uint32_t kbase = sb + SK + b * 33792;
        float s[4][4];
        #pragma unroll
        for (int i = 0; i < 4; i++)
            #pragma unroll
            for (int j = 0; j < 4; j++) s[i][j] = 0.f;
        #pragma unroll
        for (int k = 0; k < 16; k++) {
            uint32_t Qa[4];
            ldm4(Qa, sb + SQ + qrow * 528 + (qcol + k * 16) * 2);
            #pragma unroll
            for (int np = 0; np < 2; np++) {
                uint32_t bf[4];
                ldm4(bf, kbase + (ch * 32 + np * 16 + krow_off) * 528 + (k * 16 + kcol_off) * 2);
                mma16816(s[np * 2],     Qa, bf[0], bf[1]);
                mma16816(s[np * 2 + 1], Qa, bf[2], bf[3]);
            }
        }

        // ---- decay + private online softmax ----
        const float4* pk = (const float4*)(sm + SPK + b * 1024);
        float mxA = -1e30f, mxB = -1e30f;
        #pragma unroll
        for (int nb = 0; nb < 4; nb++) {
            int c0 = ch * 32 + nb * 8 + t4 * 2;
            float4 k0 = pk[c0], k1 = pk[c0 + 1];
            float dA0 = pqA.w + k0.w - 2.f*(pqA.x*k0.x + pqA.y*k0.y + pqA.z*k0.z);
            float dA1 = pqA.w + k1.w - 2.f*(pqA.x*k1.x + pqA.y*k1.y + pqA.z*k1.z);
            float dB0 = pqB.w + k0.w - 2.f*(pqB.x*k0.x + pqB.y*k0.y + pqB.z*k0.z);
            float dB1 = pqB.w + k1.w - 2.f*(pqB.x*k1.x + pqB.y*k1.y + pqB.z*k1.z);
            s[nb][0] *= __expf(-0.5f * fmaxf(dA0, 0.f));
            s[nb][1] *= __expf(-0.5f * fmaxf(dA1, 0.f));
            s[nb][2] *= __expf(-0.5f * fmaxf(dB0, 0.f));
            s[nb][3] *= __expf(-0.5f * fmaxf(dB1, 0.f));
            mxA = fmaxf(mxA, fmaxf(s[nb][0], s[nb][1]));
            mxB = fmaxf(mxB, fmaxf(s[nb][2], s[nb][3]));
        }
        mxA = fmaxf(mxA, __shfl_xor_sync(0xffffffffu, mxA, 1));
        mxA = fmaxf(mxA, __shfl_xor_sync(0xffffffffu, mxA, 2));
        mxB = fmaxf(mxB, __shfl_xor_sync(0xffffffffu, mxB, 1));
        mxB = fmaxf(mxB, __shfl_xor_sync(0xffffffffu, mxB, 2));

        float sclA = 1.f, sclB = 1.f;
        bool upd = (mxA > mA) || (mxB > mB);
        if (__any_sync(0xffffffffu, upd)) {
            float nMA = fmaxf(mA, mxA), nMB = fmaxf(mB, mxB);
            sclA = __expf(mA - nMA); sclB = __expf(mB - nMB);
            mA = nMA; mB = nMB;
            #pragma unroll
            for (int nb = 0; nb < 32; nb++) {
                o[nb][0] *= sclA; o[nb][1] *= sclA;
                o[nb][2] *= sclB; o[nb][3] *= sclB;
            }
        }

        float smA = 0.f, smB = 0.f;
        #pragma unroll
        for (int nb = 0; nb < 4; nb++) {
            float p0 = __expf(s[nb][0] - mA);
            float p1 = __expf(s[nb][1] - mA);
            float p2 = __expf(s[nb][2] - mB);
            float p3 = __expf(s[nb][3] - mB);
            smA += p0 + p1; smB += p2 + p3;
            s[nb][0] = p0; s[nb][1] = p1; s[nb][2] = p2; s[nb][3] = p3;
        }
        smA += __shfl_xor_sync(0xffffffffu, smA, 1);
        smA += __shfl_xor_sync(0xffffffffu, smA, 2);
        smB += __shfl_xor_sync(0xffffffffu, smB, 1);
        smB += __shfl_xor_sync(0xffffffffu, smB, 2);
        lA = lA * sclA + smA;
        lB = lB * sclB + smB;

        // pack P a-frags (C-layout == A-layout)
        uint32_t aa[2][4];
        #pragma unroll
        for (int ks = 0; ks < 2; ks++) {
            aa[ks][0] = pack_bf16(s[ks*2][0],   s[ks*2][1]);
            aa[ks][1] = pack_bf16(s[ks*2][2],   s[ks*2][3]);
            aa[ks][2] = pack_bf16(s[ks*2+1][0], s[ks*2+1][1]);
            aa[ks][3] = pack_bf16(s[ks*2+1][2], s[ks*2+1][3]);
        }

        // ---- O += P V (warp: 16 rows x 256 dims, its 32 keys) ----
        const uint32_t vbase = sb + SV + b * 33792;
        #pragma unroll
        for (int ks = 0; ks < 2; ks++) {
            #pragma unroll
            for (int n16 = 0; n16 < 16; n16++) {
                uint32_t vb[4];
                ldm4t(vb, vbase + (ch * 32 + ks * 16 + vrow_off) * 528 + (n16 * 16 + vcol_off) * 2);
                mma16816(o[n16 * 2],     aa[ks], vb[0], vb[1]);
                mma16816(o[n16 * 2 + 1], aa[ks], vb[2], vb[3]);
            }
        }
        __syncthreads();
        if (tt + 2 < 128) load_tile(sb, t, tt + 2);
        else asm volatile("cp.async.commit_group;" ::: "memory");
    }

    // ---- merge ch halves ----
    float* oM = (float*)sm;               // [64][260]
    float* mS = (float*)(sm + 68608);     // m[64], l[64]
    if (ch == 1) {
        #pragma unroll
        for (int nb = 0; nb < 32; nb++) {
            int c = nb * 8 + t4 * 2;
            oM[rA * 260 + c] = o[nb][0]; oM[rA * 260 + c + 1] = o[nb][1];
            oM[rB * 260 + c] = o[nb][2]; oM[rB * 260 + c + 1] = o[nb][3];
        }
        if (t4 == 0) { mS[rA] = mA; mS[64 + rA] = lA; mS[rB] = mB; mS[64 + rB] = lB; }
    }
    __syncthreads();
    if (ch == 0) {
        float m1A = mS[rA], l1A = mS[64 + rA];
        float m1B = mS[rB], l1B = mS[64 + rB];
        float MA = fmaxf(mA, m1A), MB = fmaxf(mB, m1B);
        float e0A = __expf(mA - MA), e1A = __expf(m1A - MA);
        float e0B = __expf(mB - MB), e1B = __expf(m1B - MB);
        float invA = 1.f / (1.f + lA * e0A + l1A * e1A);
        float invB = 1.f / (1.f + lB * e0B + l1B * e1B);
        const int gA = i0 + rA, gB = i0 + rB;
        #pragma unroll
        for (int nb = 0; nb < 32; nb++) {
            int c = nb * 8 + t4 * 2;
            float2 vA, vB;
            vA.x = (o[nb][0] * e0A + oM[rA * 260 + c]     * e1A) * invA + X[(size_t)gA * XSTR + c];
            vA.y = (o[nb][1] * e0A + oM[rA * 260 + c + 1] * e1A) * invA + X[(size_t)gA * XSTR + c + 1];
            vB.x = (o[nb][2] * e0B + oM[rB * 260 + c]     * e1B) * invB + X[(size_t)gB * XSTR + c];
            vB.y = (o[nb][3] * e0B + oM[rB * 260 + c + 1] * e1B) * invB + X[(size_t)gB * XSTR + c + 1];
            *(float2*)&out[(size_t)gA * DD + c] = vA;
            *(float2*)&out[(size_t)gB * DD + c] = vB;
        }
    }
}

// ---------------------------------------------------------------------------
extern "C" void kernel_launch(void* const* d_in, const int* in_sizes, int n_in,
                              void* d_out, int out_size)
{
    const float* X  = (const float*)d_in[0];
    const float* WQ = (const float*)d_in[1];
    const float* bQ = (const float*)d_in[2];
    const float* WK = (const float*)d_in[3];
    const float* bK = (const float*)d_in[4];
    const float* WV = (const float*)d_in[5];
    const float* bV = (const float*)d_in[6];
    float* out = (float*)d_out;

    cudaFuncSetAttribute(flash_kernel, cudaFuncAttributeMaxDynamicSharedMemorySize, SMEMB);
    cudaFuncSetAttribute(qkv_mma_kernel, cudaFuncAttributeMaxDynamicSharedMemorySize, SMEMQ);

    prep_kernel<<<NN * 32 / 256, 256>>>(X);
    wconv_kernel<<<dim3(DD * DD / 8 / 256, 3), 256>>>(WQ, WK, WV);
    qkv_mma_kernel<<<dim3(NN / 128, 3), 256, SMEMQ>>>(bQ, bK, bV);
    flash_kernel<<<NN / 64, 256, SMEMB>>>(X, out);
}

// round 6
// speedup vs baseline: 6.4541x; 1.0789x over previous
#include <cuda_runtime.h>
#include <cuda_bf16.h>
#include <cstdint>

#define NN 8192
#define DD 256
#define XSTR 259

// ---------------- device scratch ----------------
__device__ __nv_bfloat16 g_Xbf[NN * DD];      // X features bf16
__device__ __nv_bfloat16 g_Wbf[3][DD * DD];   // W bf16 [k][n] (Q folded w/ 1/16)
__device__ __nv_bfloat16 g_Qbf[NN * DD];      // Q/16 bf16
__device__ __nv_bfloat16 g_Kbf[NN * DD];
__device__ __nv_bfloat16 g_Vbf[NN * DD];
__device__ float4 g_P4[NN];                   // px,py,pz,|p|^2

// ---------------- helpers ----------------
__device__ __forceinline__ uint32_t smem_u32(const void* p) {
    uint32_t a;
    asm("{ .reg .u64 t; cvta.to.shared.u64 t, %1; cvt.u32.u64 %0, t; }" : "=r"(a) : "l"(p));
    return a;
}
__device__ __forceinline__ uint32_t pack_bf16(float lo, float hi) {
    uint32_t r;
    asm("cvt.rn.bf16x2.f32 %0, %1, %2;" : "=r"(r) : "f"(hi), "f"(lo));
    return r;
}
__device__ __forceinline__ void cp16(uint32_t s, const void* g) {
    asm volatile("cp.async.cg.shared.global [%0], [%1], 16;" :: "r"(s), "l"(g));
}
__device__ __forceinline__ void ldm4(uint32_t* r, uint32_t a) {
    asm volatile("ldmatrix.sync.aligned.m8n8.x4.shared.b16 {%0,%1,%2,%3}, [%4];"
                 : "=r"(r[0]), "=r"(r[1]), "=r"(r[2]), "=r"(r[3]) : "r"(a));
}
__device__ __forceinline__ void ldm4t(uint32_t* r, uint32_t a) {
    asm volatile("ldmatrix.sync.aligned.m8n8.x4.trans.shared.b16 {%0,%1,%2,%3}, [%4];"
                 : "=r"(r[0]), "=r"(r[1]), "=r"(r[2]), "=r"(r[3]) : "r"(a));
}
__device__ __forceinline__ void mma16816(float* c, const uint32_t* a, uint32_t b0, uint32_t b1) {
    asm volatile(
        "mma.sync.aligned.m16n8k16.row.col.f32.bf16.bf16.f32 "
        "{%0,%1,%2,%3}, {%4,%5,%6,%7}, {%8,%9}, {%0,%1,%2,%3};"
        : "+f"(c[0]), "+f"(c[1]), "+f"(c[2]), "+f"(c[3])
        : "r"(a[0]), "r"(a[1]), "r"(a[2]), "r"(a[3]), "r"(b0), "r"(b1));
}

// ---------------------------------------------------------------------------
// K0: prep — X -> bf16, positions.  (X rows only 4B-aligned: scalar loads)
// ---------------------------------------------------------------------------
__global__ __launch_bounds__(256) void prep_kernel(const float* __restrict__ X)
{
    int idx = blockIdx.x * 256 + threadIdx.x;
    int row = idx >> 5, c8 = idx & 31;
    const float* xr = X + (size_t)row * XSTR + c8 * 8;
    float v0 = xr[0], v1 = xr[1], v2 = xr[2], v3 = xr[3];
    float v4 = xr[4], v5 = xr[5], v6 = xr[6], v7 = xr[7];
    uint4 u;
    u.x = pack_bf16(v0, v1); u.y = pack_bf16(v2, v3);
    u.z = pack_bf16(v4, v5); u.w = pack_bf16(v6, v7);
    *(uint4*)&g_Xbf[(size_t)row * DD + c8 * 8] = u;
    if (c8 == 0) {
        float px = X[(size_t)row * XSTR + 256];
        float py = X[(size_t)row * XSTR + 257];
        float pz = X[(size_t)row * XSTR + 258];
        g_P4[row] = make_float4(px, py, pz, px*px + py*py + pz*pz);
    }
}

// ---------------------------------------------------------------------------
// K0b: W -> bf16 (Q folded with 1/16)
// ---------------------------------------------------------------------------
__global__ __launch_bounds__(256) void wconv_kernel(
    const float* __restrict__ WQ, const float* __restrict__ WK, const float* __restrict__ WV)
{
    int mat = blockIdx.y;
    const float* W = (mat == 0) ? WQ : (mat == 1) ? WK : WV;
    float sc = (mat == 0) ? 0.0625f : 1.0f;
    int idx = blockIdx.x * 256 + threadIdx.x;
    int base = idx * 8;
    const float4* wr = (const float4*)(W + base);
    float4 a = wr[0], b = wr[1];
    uint4 u;
    u.x = pack_bf16(a.x*sc, a.y*sc); u.y = pack_bf16(a.z*sc, a.w*sc);
    u.z = pack_bf16(b.x*sc, b.y*sc); u.w = pack_bf16(b.z*sc, b.w*sc);
    *(uint4*)&g_Wbf[mat][base] = u;
}

// ---------------------------------------------------------------------------
// K1: QKV via mma.sync.  grid (64, 3), 256 thr, warp = 16 rows x 256 cols
// ---------------------------------------------------------------------------
#define QX 0                  // 128 x 528
#define QW 67584              // 256 x 528
#define SMEMQ (67584 + 135168)

__global__ __launch_bounds__(256, 1) void qkv_mma_kernel(
    const float* __restrict__ bQ, const float* __restrict__ bK, const float* __restrict__ bV)
{
    extern __shared__ char sm[];
    const uint32_t sb = smem_u32(sm);
    const int t = threadIdx.x, lane = t & 31, w = t >> 5;
    const int g = lane >> 2, t4 = lane & 3;
    const int mat = blockIdx.y;
    const int i0 = blockIdx.x * 128;
    const float* bias = (mat == 0) ? bQ : (mat == 1) ? bK : bV;
    const float bsc = (mat == 0) ? 0.0625f : 1.0f;
    __nv_bfloat16* O = (mat == 0) ? g_Qbf : (mat == 1) ? g_Kbf : g_Vbf;

    #pragma unroll
    for (int l = 0; l < 16; l++) {
        int idx = t + l * 256;
        int r = idx >> 5, c8 = idx & 31;
        uint4 v = *(const uint4*)&g_Xbf[(size_t)(i0 + r) * DD + c8 * 8];
        *(uint4*)(sm + QX + r * 528 + c8 * 16) = v;
    }
    #pragma unroll
    for (int l = 0; l < 32; l++) {
        int idx = t + l * 256;
        int r = idx >> 5, c8 = idx & 31;
        uint4 v = *(const uint4*)&g_Wbf[mat][(size_t)r * DD + c8 * 8];
        *(uint4*)(sm + QW + r * 528 + c8 * 16) = v;
    }
    __syncthreads();

    float o[32][4];
    #pragma unroll
    for (int i = 0; i < 32; i++)
        #pragma unroll
        for (int j = 0; j < 4; j++) o[i][j] = 0.f;

    const int arow = w * 16 + (lane & 15);
    const int acol = (lane >> 4) * 8;
    const int vrow_off = ((lane >> 3) & 1) * 8 + (lane & 7);
    const int vcol_off = (lane >> 4) * 8;

    #pragma unroll
    for (int k = 0; k < 16; k++) {
        uint32_t Aa[4];
        ldm4(Aa, sb + QX + arow * 528 + (acol + k * 16) * 2);
        #pragma unroll
        for (int n16 = 0; n16 < 16; n16++) {
            uint32_t vb[4];
            ldm4t(vb, sb + QW + (k * 16 + vrow_off) * 528 + (n16 * 16 + vcol_off) * 2);
            mma16816(o[n16 * 2],     Aa, vb[0], vb[1]);
            mma16816(o[n16 * 2 + 1], Aa, vb[2], vb[3]);
        }
    }

    const int row0 = i0 + w * 16 + g;
    #pragma unroll
    for (int nb = 0; nb < 32; nb++) {
        int c = nb * 8 + t4 * 2;
        float b0 = bias[c] * bsc, b1 = bias[c + 1] * bsc;
        *(uint32_t*)&O[(size_t)row0 * DD + c]       = pack_bf16(o[nb][0] + b0, o[nb][1] + b1);
        *(uint32_t*)&O[(size_t)(row0 + 8) * DD + c] = pack_bf16(o[nb][2] + b0, o[nb][3] + b1);
    }
}

// ---------------------------------------------------------------------------
// K2: flash attention, UNSHIFTED exp accumulation (softmax-one exact via
// H = sum(e^x V) / (e^max + sum(e^x)); max tracked privately, reduced once)
// grid 128 CTAs x 64 rows; 8 warps = (rg 0..3) x (key-half ch 0..1)
// ---------------------------------------------------------------------------
#define SQ   0                       // 64*528 = 33792
#define SK   33792                   // 2 x 33792
#define SV   101376                  // 2 x 33792
#define SPK  168960                  // 2 x 1024
#define SMEMB 171008
// merge area (after loop): oM f32 [64][260] at 0; m/l at 68608

__device__ __forceinline__ void load_tile(uint32_t sb, int t, int tt)
{
    const int b = tt & 1;
    const int j0 = tt * 64;
    #pragma unroll
    for (int l = 0; l < 8; l++) {
        int idx = t + l * 256;
        int r = idx >> 5, c8 = idx & 31;
        size_t goff = ((size_t)(j0 + r) * DD + c8 * 8) * 2;
        uint32_t soff = (uint32_t)(r * 528 + c8 * 16);
        cp16(sb + SK + b * 33792 + soff, (const char*)g_Kbf + goff);
        cp16(sb + SV + b * 33792 + soff, (const char*)g_Vbf + goff);
    }
    if (t < 64) cp16(sb + SPK + b * 1024 + t * 16, &g_P4[j0 + t]);
    asm volatile("cp.async.commit_group;" ::: "memory");
}

__global__ __launch_bounds__(256, 1) void flash_kernel(
    const float* __restrict__ X, float* __restrict__ out)
{
    extern __shared__ char sm[];
    const uint32_t sb = smem_u32(sm);
    const int t = threadIdx.x;
    const int lane = t & 31, w = t >> 5;
    const int rg = w & 3, ch = w >> 2;
    const int g = lane >> 2, t4 = lane & 3;
    const int i0 = blockIdx.x * 64;
    const int rA = rg * 16 + g, rB = rA + 8;

    // stage Q
    #pragma unroll
    for (int l = 0; l < 8; l++) {
        int idx = t + l * 256;
        int r = idx >> 5, c8 = idx & 31;
        uint4 v = *(const uint4*)&g_Qbf[(size_t)(i0 + r) * DD + c8 * 8];
        *(uint4*)(sm + SQ + r * 528 + c8 * 16) = v;
    }
    load_tile(sb, t, 0);
    load_tile(sb, t, 1);

    const float4 pqA = g_P4[i0 + rA];
    const float4 pqB = g_P4[i0 + rB];

    float o[32][4];
    #pragma unroll
    for (int i = 0; i < 32; i++)
        #pragma unroll
        for (int j = 0; j < 4; j++) o[i][j] = 0.f;
    float mA = -1e30f, mB = -1e30f;   // private running max of logits
    float lA = 0.f, lB = 0.f;         // private partial sums of e^logit

    const int qrow = rg * 16 + (lane & 15);
    const int qcol = (lane >> 4) * 8;
    const int krow_off = ((lane >> 4) << 3) + (lane & 7);
    const int kcol_off = ((lane >> 3) & 1) * 8;
    const int vrow_off = ((lane >> 3) & 1) * 8 + (lane & 7);
    const int vcol_off = (lane >> 4) * 8;

    __syncthreads();

    #pragma unroll 1
    for (int tt = 0; tt < 128; tt++) {
        const int b = tt & 1;
        asm volatile("cp.async.wait_group 1;" ::: "memory");
        __syncthreads();

        // ---- S = Q K^T (warp: 16 rows x 32 keys of its half) ----
        const uint32_t kbase = sb + SK + b * 33792;
        float s[4][4];
        #pragma unroll
        for (int i = 0; i < 4; i++)
            #pragma unroll
            for (int j = 0; j < 4; j++) s[i][j] = 0.f;
        #pragma unroll
        for (int k = 0; k < 16; k++) {
            uint32_t Qa[4];
            ldm4(Qa, sb + SQ + qrow * 528 + (qcol + k * 16) * 2);
            #pragma unroll
            for (int np = 0; np < 2; np++) {
                uint32_t bf[4];
                ldm4(bf, kbase + (ch * 32 + np * 16 + krow_off) * 528 + (k * 16 + kcol_off) * 2);
                mma16816(s[np * 2],     Qa, bf[0], bf[1]);
                mma16816(s[np * 2 + 1], Qa, bf[2], bf[3]);
            }
        }

        // ---- decay, unshifted exp, private max/sum, pack P ----
        const float4* pk = (const float4*)(sm + SPK + b * 1024);
        uint32_t aa[2][4];
        #pragma unroll
        for (int nb = 0; nb < 4; nb++) {
            int c0 = ch * 32 + nb * 8 + t4 * 2;
            float4 k0 = pk[c0], k1 = pk[c0 + 1];
            float dA0 = pqA.w + k0.w - 2.f*(pqA.x*k0.x + pqA.y*k0.y + pqA.z*k0.z);
            float dA1 = pqA.w + k1.w - 2.f*(pqA.x*k1.x + pqA.y*k1.y + pqA.z*k1.z);
            float dB0 = pqB.w + k0.w - 2.f*(pqB.x*k0.x + pqB.y*k0.y + pqB.z*k0.z);
            float dB1 = pqB.w + k1.w - 2.f*(pqB.x*k1.x + pqB.y*k1.y + pqB.z*k1.z);
            float x0 = s[nb][0] * __expf(-0.5f * fmaxf(dA0, 0.f));
            float x1 = s[nb][1] * __expf(-0.5f * fmaxf(dA1, 0.f));
            float x2 = s[nb][2] * __expf(-0.5f * fmaxf(dB0, 0.f));
            float x3 = s[nb][3] * __expf(-0.5f * fmaxf(dB1, 0.f));
            mA = fmaxf(mA, fmaxf(x0, x1));
            mB = fmaxf(mB, fmaxf(x2, x3));
            float p0 = __expf(x0), p1 = __expf(x1);
            float p2 = __expf(x2), p3 = __expf(x3);
            lA += p0 + p1; lB += p2 + p3;
            // pack into A-fragment layout: aa[ks][0..3], ks = nb>>1
            if ((nb & 1) == 0) {
                aa[nb >> 1][0] = pack_bf16(p0, p1);
                aa[nb >> 1][1] = pack_bf16(p2, p3);
            } else {
                aa[nb >> 1][2] = pack_bf16(p0, p1);
                aa[nb >> 1][3] = pack_bf16(p2, p3);
            }
        }

        // ---- O += P V (warp: 16 rows x 256 dims, its 32 keys) ----
        const uint32_t vbase = sb + SV + b * 33792;
        #pragma unroll
        for (int ks = 0; ks < 2; ks++) {
            #pragma unroll
            for (int n16 = 0; n16 < 16; n16++) {
                uint32_t vb[4];
                ldm4t(vb, vbase + (ch * 32 + ks * 16 + vrow_off) * 528 + (n16 * 16 + vcol_off) * 2);
                mma16816(o[n16 * 2],     aa[ks], vb[0], vb[1]);
                mma16816(o[n16 * 2 + 1], aa[ks], vb[2], vb[3]);
            }
        }
        __syncthreads();
        if (tt + 2 < 128) load_tile(sb, t, tt + 2);
        else asm volatile("cp.async.commit_group;" ::: "memory");
    }

    // ---- reduce private l/m over the quad (t4 lanes) ----
    lA += __shfl_xor_sync(0xffffffffu, lA, 1);
    lA += __shfl_xor_sync(0xffffffffu, lA, 2);
    lB += __shfl_xor_sync(0xffffffffu, lB, 1);
    lB += __shfl_xor_sync(0xffffffffu, lB, 2);
    mA = fmaxf(mA, __shfl_xor_sync(0xffffffffu, mA, 1));
    mA = fmaxf(mA, __shfl_xor_sync(0xffffffffu, mA, 2));
    mB = fmaxf(mB, __shfl_xor_sync(0xffffffffu, mB, 1));
    mB = fmaxf(mB, __shfl_xor_sync(0xffffffffu, mB, 2));

    // ---- merge ch halves (raw sums: just add) ----
    float* oM = (float*)sm;               // [64][260]
    float* mS = (float*)(sm + 68608);     // m[64], l[64]
    if (ch == 1) {
        #pragma unroll
        for (int nb = 0; nb < 32; nb++) {
            int c = nb * 8 + t4 * 2;
            oM[rA * 260 + c] = o[nb][0]; oM[rA * 260 + c + 1] = o[nb][1];
            oM[rB * 260 + c] = o[nb][2]; oM[rB * 260 + c + 1] = o[nb][3];
        }
        if (t4 == 0) { mS[rA] = mA; mS[64 + rA] = lA; mS[rB] = mB; mS[64 + rB] = lB; }
    }
    __syncthreads();
    if (ch == 0) {
        float MA = fmaxf(mA, mS[rA]), MB = fmaxf(mB, mS[rB]);
        float invA = 1.f / (__expf(MA) + lA + mS[64 + rA]);
        float invB = 1.f / (__expf(MB) + lB + mS[64 + rB]);
        const int gA = i0 + rA, gB = i0 + rB;
        #pragma unroll
        for (int nb = 0; nb < 32; nb++) {
            int c = nb * 8 + t4 * 2;
            float2 vA, vB;
            vA.x = (o[nb][0] + oM[rA * 260 + c])     * invA + X[(size_t)gA * XSTR + c];
            vA.y = (o[nb][1] + oM[rA * 260 + c + 1]) * invA + X[(size_t)gA * XSTR + c + 1];
            vB.x = (o[nb][2] + oM[rB * 260 + c])     * invB + X[(size_t)gB * XSTR + c];
            vB.y = (o[nb][3] + oM[rB * 260 + c + 1]) * invB + X[(size_t)gB * XSTR + c + 1];
            *(float2*)&out[(size_t)gA * DD + c] = vA;
            *(float2*)&out[(size_t)gB * DD + c] = vB;
        }
    }
}

// ---------------------------------------------------------------------------
extern "C" void kernel_launch(void* const* d_in, const int* in_sizes, int n_in,
                              void* d_out, int out_size)
{
    const float* X  = (const float*)d_in[0];
    const float* WQ = (const float*)d_in[1];
    const float* bQ = (const float*)d_in[2];
    const float* WK = (const float*)d_in[3];
    const float* bK = (const float*)d_in[4];
    const float* WV = (const float*)d_in[5];
    const float* bV = (const float*)d_in[6];
    float* out = (float*)d_out;

    cudaFuncSetAttribute(flash_kernel, cudaFuncAttributeMaxDynamicSharedMemorySize, SMEMB);
    cudaFuncSetAttribute(qkv_mma_kernel, cudaFuncAttributeMaxDynamicSharedMemorySize, SMEMQ);

    prep_kernel<<<NN * 32 / 256, 256>>>(X);
    wconv_kernel<<<dim3(DD * DD / 8 / 256, 3), 256>>>(WQ, WK, WV);
    qkv_mma_kernel<<<dim3(NN / 128, 3), 256, SMEMQ>>>(bQ, bK, bV);
    flash_kernel<<<NN / 64, 256, SMEMB>>>(X, out);
}